// round 14
// baseline (speedup 1.0000x reference)
#include <cuda_runtime.h>
#include <math.h>
#include <stdint.h>

// Problem dims
#define BB 2
#define CC 128
#define HH 48
#define WW 48
#define GG 4
#define DHD 32
#define NPIX 2304   // 48*48
#define HD 12
#define JD 144      // 12*12
#define BG 8        // B*G
#define TI 16       // query tile per attention block
#define BSTR 145    // padded bias row stride
#define H1PAD 36    // h1 tile row stride (uint32): conflict-free frag loads

// Scratch (allocation-free: __device__ globals)
__device__ float g_q[BG * DHD * NPIX];   // q per (bg, d, i)
__device__ float g_vn0[BG * JD];
__device__ float g_vn1[BG * JD];
__device__ float g_k[BG * JD * DHD];     // (bg, j, d)
__device__ float g_v[BG * JD * DHD];
__device__ float g_o[BB * CC * NPIX];    // attention head outputs

__device__ __forceinline__ uint32_t f2tf32(float x) {
    uint32_t u;
    asm("cvt.rna.tf32.f32 %0, %1;" : "=r"(u) : "f"(x));
    return u;
}

// ---------------------------------------------------------------------------
// K1: grouped 1x1 conv -> q.  grid (18, 8), block 128.
// ---------------------------------------------------------------------------
__global__ void __launch_bounds__(128)
k_qproj(const float* __restrict__ x, const float* __restrict__ wq) {
    int bg = blockIdx.y;
    int g  = bg & 3;
    int b  = bg >> 2;
    int i  = blockIdx.x * 128 + threadIdx.x;

    __shared__ __align__(16) float wqs[32 * 32];
    for (int t = threadIdx.x; t < 1024; t += 128) wqs[t] = wq[g * 1024 + t];
    __syncthreads();
    if (i >= NPIX) return;

    float acc[32];
#pragma unroll
    for (int o = 0; o < 32; o++) acc[o] = 0.f;

    const float* xp = x + (size_t)(b * CC + g * 32) * NPIX + i;
#pragma unroll 4
    for (int c = 0; c < 32; c++) {
        float xv = xp[c * NPIX];
#pragma unroll
        for (int o = 0; o < 32; o++) acc[o] = fmaf(xv, wqs[o * 32 + c], acc[o]);
    }
#pragma unroll
    for (int o = 0; o < 32; o++) g_q[(bg * 32 + o) * NPIX + i] = acc[o];
}

// ---------------------------------------------------------------------------
// K2: offsets + bilinear + k/v proj.  grid (8, 12), block 384.
// ---------------------------------------------------------------------------
__global__ void __launch_bounds__(384)
k_offsets(const float* __restrict__ x,
          const float* __restrict__ wdw, const float* __restrict__ bdw,
          const float* __restrict__ wproj,
          const float* __restrict__ wk, const float* __restrict__ wv) {
    int bg = blockIdx.x;
    int g  = bg & 3;
    int b  = bg >> 2;
    int oy = blockIdx.y;
    int t  = threadIdx.x;
    int ox = t >> 5;
    int c  = t & 31;
    int j  = oy * HD + ox;

    __shared__ float wks[32 * 33], wvs[32 * 33];
    __shared__ float kvs[12][33];

    for (int idx = t; idx < 1024; idx += 384) {
        int o = idx >> 5, cc = idx & 31;
        wks[o * 33 + cc] = wk[g * 1024 + idx];
        wvs[o * 33 + cc] = wv[g * 1024 + idx];
    }

    float s = 0.f;
    const float* qc = g_q + (size_t)(bg * 32 + c) * NPIX;
    const float* wc = wdw + c * 36;
#pragma unroll
    for (int ky = 0; ky < 6; ky++) {
        int iy = oy * 4 - 1 + ky;
        if (iy < 0 || iy >= HH) continue;
#pragma unroll
        for (int kx = 0; kx < 6; kx++) {
            int ix = ox * 4 - 1 + kx;
            if (ix < 0 || ix >= WW) continue;
            s = fmaf(qc[iy * WW + ix], wc[ky * 6 + kx], s);
        }
    }
    float tt = s + bdw[c];
    float ge = 0.5f * tt * (1.f + erff(tt * 0.70710678118654752f));
    float p0 = ge * wproj[c];
    float p1 = ge * wproj[32 + c];
#pragma unroll
    for (int off = 16; off > 0; off >>= 1) {
        p0 += __shfl_xor_sync(0xffffffffu, p0, off);
        p1 += __shfl_xor_sync(0xffffffffu, p1, off);
    }

    float px = 0.f, py = 0.f;
    if (c == 0) {
        float o0 = tanhf(p0) * 4.f;
        float o1 = tanhf(p1) * 4.f;
        float vn0 = 2.f * ((float)ox + o0) / 11.f - 1.f;
        float vn1 = 2.f * ((float)oy + o1) / 11.f - 1.f;
        g_vn0[bg * JD + j] = vn0;
        g_vn1[bg * JD + j] = vn1;
        px = ((vn0 + 1.f) * (float)WW - 1.f) * 0.5f;
        py = ((vn1 + 1.f) * (float)HH - 1.f) * 0.5f;
    }
    px = __shfl_sync(0xffffffffu, px, 0);
    py = __shfl_sync(0xffffffffu, py, 0);

    float x0 = floorf(px), y0 = floorf(py);
    float wx1 = px - x0, wy1 = py - y0;
    int ix0 = (int)x0, iy0 = (int)y0;
    float w00 = (1.f - wx1) * (1.f - wy1);
    float w10 = wx1 * (1.f - wy1);
    float w01 = (1.f - wx1) * wy1;
    float w11 = wx1 * wy1;
    bool vx0 = (ix0 >= 0) && (ix0 <= WW - 1);
    bool vx1 = (ix0 + 1 >= 0) && (ix0 + 1 <= WW - 1);
    bool vy0 = (iy0 >= 0) && (iy0 <= HH - 1);
    bool vy1 = (iy0 + 1 >= 0) && (iy0 + 1 <= HH - 1);
    int cx0 = min(max(ix0, 0), WW - 1), cx1 = min(max(ix0 + 1, 0), WW - 1);
    int cy0 = min(max(iy0, 0), HH - 1), cy1 = min(max(iy0 + 1, 0), HH - 1);

    const float* xc = x + (size_t)(b * CC + g * 32 + c) * NPIX;
    float a = 0.f;
    if (vx0 && vy0) a = fmaf(xc[cy0 * WW + cx0], w00, a);
    if (vx1 && vy0) a = fmaf(xc[cy0 * WW + cx1], w10, a);
    if (vx0 && vy1) a = fmaf(xc[cy1 * WW + cx0], w01, a);
    if (vx1 && vy1) a = fmaf(xc[cy1 * WW + cx1], w11, a);
    kvs[ox][c] = a;
    __syncthreads();

    int o = c;
    float ak = 0.f, av = 0.f;
#pragma unroll 8
    for (int cc = 0; cc < 32; cc++) {
        float kvv = kvs[ox][cc];
        ak = fmaf(kvv, wks[o * 33 + cc], ak);
        av = fmaf(kvv, wvs[o * 33 + cc], av);
    }
    g_k[(size_t)(bg * JD + j) * 32 + o] = ak;
    g_v[(size_t)(bg * JD + j) * 32 + o] = av;
}

// ---------------------------------------------------------------------------
// K3: fused attention, two phases.  grid (8, 144), block 128.  TI=16.
//   Phase A layer-1: tf32 mma.sync.m16n8k8; h1 raw fp32 bits (HW truncation).
//   Phase B: 8 threads per query (4 dims each), shfl tree over 8 lanes.
// ---------------------------------------------------------------------------
__global__ void __launch_bounds__(128)
k_attn(const float* __restrict__ cw0, const float* __restrict__ cb0,
       const float* __restrict__ cw1, const float* __restrict__ cb1,
       const float* __restrict__ cw2, const float* __restrict__ cb2) {
    int bg = blockIdx.x;
    int ib = blockIdx.y * TI;
    int t  = threadIdx.x;
    int wp   = t >> 5;
    int lane = t & 31;

    __shared__ __align__(16) float bias_s[TI * BSTR];
    __shared__ __align__(16) uint32_t h1s[4][32 * H1PAD];  // per-warp h1 tile (fp32 bits)
    __shared__ __align__(16) uint2 w1f[4][4][32];          // B fragments [ktile][ntile][lane]
    __shared__ float vn0s[JD], vn1s[JD];
    __shared__ float w0s[64], b0s[32], b1s[32], w2s[32];

    for (int idx = t; idx < JD; idx += 128) {
        vn0s[idx] = g_vn0[bg * JD + idx];
        vn1s[idx] = g_vn1[bg * JD + idx];
    }
    if (t < 64) w0s[t] = cw0[t];
    if (t < 32) { b0s[t] = cb0[t]; b1s[t] = cb1[t]; w2s[t] = cw2[t]; }
    for (int idx = t; idx < 512; idx += 128) {
        int kt = idx >> 7;
        int nt = (idx >> 5) & 3;
        int ln = idx & 31;
        int k  = kt * 8 + (ln & 3);
        int n  = nt * 8 + (ln >> 2);
        uint2 bfr;
        bfr.x = f2tf32(cw1[k * 32 + n]);         // b0: (k, n)
        bfr.y = f2tf32(cw1[(k + 4) * 32 + n]);   // b1: (k+4, n)
        w1f[kt][nt][ln] = bfr;
    }
    __syncthreads();

    float b2v = __ldg(cb2);

    // Per-lane epilogue constants: this lane's 8 output channels (2 per ntile).
    float b1v[8], w2v[8];
#pragma unroll
    for (int nt = 0; nt < 4; nt++) {
        int c = nt * 8 + 2 * (lane & 3);
        b1v[2 * nt]     = b1s[c];
        b1v[2 * nt + 1] = b1s[c + 1];
        w2v[2 * nt]     = w2s[c];
        w2v[2 * nt + 1] = w2s[c + 1];
    }

    uint32_t* hw = &h1s[wp][0];
    int r0 = lane >> 2;
    int c0 = lane & 3;

    // -------- Phase A: 18 passes, 32 evals per warp per pass --------
#pragma unroll 1
    for (int pass = 0; pass < 18; pass++) {
        int pbase = pass * 128 + wp * 32;
        int p  = pbase + lane;
        int il = p / JD;
        int j  = p - il * JD;
        int i  = ib + il;
        int ixq = i % WW;
        int iyq = i / WW;
        float qn0 = fmaf((float)ixq, 2.f / 47.f, -1.f);
        float qn1 = fmaf((float)iyq, 2.f / 47.f, -1.f);
        float dx = qn0 - vn0s[j];
        float dy = qn1 - vn1s[j];
        float fx = copysignf(log1pf(fabsf(dx)), dx);
        float fy = copysignf(log1pf(fabsf(dy)), dy);

        // layer 0: 2 -> 32, relu; store straight to tile (raw fp32 bits)
        uint4* dst = (uint4*)&hw[lane * H1PAD];
#pragma unroll
        for (int q = 0; q < 8; q++) {
            int c = q * 4;
            uint4 v;
            v.x = __float_as_uint(fmaxf(fmaf(fy, w0s[32 + c],     fmaf(fx, w0s[c],     b0s[c])),     0.f));
            v.y = __float_as_uint(fmaxf(fmaf(fy, w0s[32 + c + 1], fmaf(fx, w0s[c + 1], b0s[c + 1])), 0.f));
            v.z = __float_as_uint(fmaxf(fmaf(fy, w0s[32 + c + 2], fmaf(fx, w0s[c + 2], b0s[c + 2])), 0.f));
            v.w = __float_as_uint(fmaxf(fmaf(fy, w0s[32 + c + 3], fmaf(fx, w0s[c + 3], b0s[c + 3])), 0.f));
            dst[q] = v;
        }
        __syncwarp();

        // 32x32x32 GEMM: h2 = h1 @ W1
        float acc[2][4][4];
#pragma unroll
        for (int m = 0; m < 2; m++)
#pragma unroll
            for (int n = 0; n < 4; n++)
#pragma unroll
                for (int e = 0; e < 4; e++) acc[m][n][e] = 0.f;

#pragma unroll
        for (int kt = 0; kt < 4; kt++) {
            uint32_t a[2][4];
#pragma unroll
            for (int m = 0; m < 2; m++) {
                int rb = m * 16 + r0;
                int cb = kt * 8 + c0;
                a[m][0] = hw[rb * H1PAD + cb];
                a[m][1] = hw[(rb + 8) * H1PAD + cb];
                a[m][2] = hw[rb * H1PAD + cb + 4];
                a[m][3] = hw[(rb + 8) * H1PAD + cb + 4];
            }
#pragma unroll
            for (int nt = 0; nt < 4; nt++) {
                uint2 bfr = w1f[kt][nt][lane];
#pragma unroll
                for (int m = 0; m < 2; m++) {
                    asm volatile(
                        "mma.sync.aligned.m16n8k8.row.col.f32.tf32.tf32.f32 "
                        "{%0,%1,%2,%3}, {%4,%5,%6,%7}, {%8,%9}, {%0,%1,%2,%3};"
                        : "+f"(acc[m][nt][0]), "+f"(acc[m][nt][1]),
                          "+f"(acc[m][nt][2]), "+f"(acc[m][nt][3])
                        : "r"(a[m][0]), "r"(a[m][1]), "r"(a[m][2]), "r"(a[m][3]),
                          "r"(bfr.x), "r"(bfr.y));
                }
            }
        }
        __syncwarp();   // tile reused next pass

        // layer 2: relu(h2 + b1) . w2, reduce over the 4 lanes sharing a row.
        float ps[4];
#pragma unroll
        for (int m = 0; m < 2; m++) {
            float pa = 0.f, pb = 0.f;
#pragma unroll
            for (int nt = 0; nt < 4; nt++) {
                pa = fmaf(fmaxf(acc[m][nt][0] + b1v[2 * nt],     0.f), w2v[2 * nt],     pa);
                pa = fmaf(fmaxf(acc[m][nt][1] + b1v[2 * nt + 1], 0.f), w2v[2 * nt + 1], pa);
                pb = fmaf(fmaxf(acc[m][nt][2] + b1v[2 * nt],     0.f), w2v[2 * nt],     pb);
                pb = fmaf(fmaxf(acc[m][nt][3] + b1v[2 * nt + 1], 0.f), w2v[2 * nt + 1], pb);
            }
            ps[2 * m]     = pa;   // row m*16 + r0
            ps[2 * m + 1] = pb;   // row m*16 + r0 + 8
        }
#pragma unroll
        for (int s = 0; s < 4; s++) {
            ps[s] += __shfl_xor_sync(0xffffffffu, ps[s], 1);
            ps[s] += __shfl_xor_sync(0xffffffffu, ps[s], 2);
        }
        if ((lane & 3) == 0) {
#pragma unroll
            for (int s = 0; s < 4; s++) {
                int r  = ((s >> 1) * 16) + ((s & 1) * 8) + r0;
                int pe = pbase + r;
                int ile = pe / JD;
                int je  = pe - ile * JD;
                bias_s[ile * BSTR + je] = ps[s] + b2v;
            }
        }
    }
    __syncthreads();

    // -------- Phase B: attention.  8 threads per query, 4 dims each. --------
    int il  = t >> 3;         // 0..15 query within tile
    int dqq = t & 7;          // d-eighth: 4 dims
    int i   = ib + il;

    const float scale = 0.17677669529663687f;  // 32^-0.5
    float qreg[4];
#pragma unroll
    for (int d = 0; d < 4; d++)
        qreg[d] = g_q[(bg * 32 + dqq * 4 + d) * NPIX + i] * scale;

    const float4* kb = (const float4*)(g_k + (size_t)bg * JD * 32);
    const float4* vb = (const float4*)(g_v + (size_t)bg * JD * 32);

    float m = -INFINITY, ssum = 0.f;
    float acc[4];
#pragma unroll
    for (int d = 0; d < 4; d++) acc[d] = 0.f;

#pragma unroll 2
    for (int j = 0; j < JD; j++) {
        float4 k0 = __ldg(&kb[j * 8 + dqq]);
        float sim = qreg[0] * k0.x;
        sim = fmaf(qreg[1], k0.y, sim);
        sim = fmaf(qreg[2], k0.z, sim);
        sim = fmaf(qreg[3], k0.w, sim);
        sim += __shfl_xor_sync(0xffffffffu, sim, 1);
        sim += __shfl_xor_sync(0xffffffffu, sim, 2);
        sim += __shfl_xor_sync(0xffffffffu, sim, 4);

        float logit = sim + bias_s[il * BSTR + j];

        float nm   = fmaxf(m, logit);
        float corr = __expf(m - nm);
        float p    = __expf(logit - nm);
        ssum = fmaf(ssum, corr, p);

        float4 v0 = __ldg(&vb[j * 8 + dqq]);
        acc[0] = fmaf(p, v0.x, acc[0] * corr);
        acc[1] = fmaf(p, v0.y, acc[1] * corr);
        acc[2] = fmaf(p, v0.z, acc[2] * corr);
        acc[3] = fmaf(p, v0.w, acc[3] * corr);
        m = nm;
    }

    float inv = 1.f / ssum;
#pragma unroll
    for (int d = 0; d < 4; d++)
        g_o[(bg * 32 + dqq * 4 + d) * NPIX + i] = acc[d] * inv;
}

// ---------------------------------------------------------------------------
// K4: output 1x1 projection + residual; writes both tuple outputs.
//     grid (288, 2), block 256. Tile = 8 pixels; thread = (px, 4 out chans).
// ---------------------------------------------------------------------------
__global__ void __launch_bounds__(256)
k_outproj(const float* __restrict__ x, const float* __restrict__ wo,
          const float* __restrict__ bo, const float* __restrict__ gamma,
          float* __restrict__ out, int out_size) {
    int b    = blockIdx.y;
    int t    = threadIdx.x;
    int px   = t & 7;
    int ochg = t >> 3;          // 0..31 -> out channels [ochg*4, ochg*4+4)
    int ibase = blockIdx.x * 8;

    __shared__ __align__(16) float os_s[8][132];   // [px][c], padded
    for (int idx = t; idx < 1024; idx += 256) {
        int c = idx >> 3, pl = idx & 7;
        os_s[pl][c] = g_o[(size_t)(b * CC + c) * NPIX + ibase + pl];
    }
    __syncthreads();

    float acc[4];
#pragma unroll
    for (int o = 0; o < 4; o++) acc[o] = bo[ochg * 4 + o];

#pragma unroll 4
    for (int c4 = 0; c4 < 32; c4++) {
        float4 os4 = *(const float4*)&os_s[px][c4 * 4];
#pragma unroll
        for (int o = 0; o < 4; o++) {
            float4 w4 = __ldg((const float4*)&wo[(ochg * 4 + o) * CC + c4 * 4]);
            acc[o] = fmaf(os4.x, w4.x, acc[o]);
            acc[o] = fmaf(os4.y, w4.y, acc[o]);
            acc[o] = fmaf(os4.z, w4.z, acc[o]);
            acc[o] = fmaf(os4.w, w4.w, acc[o]);
        }
    }

    float gm = gamma[0];
    const int n1 = BB * CC * NPIX;
    int i = ibase + px;
#pragma unroll
    for (int o = 0; o < 4; o++) {
        int ch  = ochg * 4 + o;
        int idx = (b * CC + ch) * NPIX + i;
        float att = acc[o];
        if (idx < out_size) out[idx] = fmaf(gm, att, x[idx]);
        int idx2 = n1 + idx;
        if (idx2 < out_size) out[idx2] = att;
    }
}

// ---------------------------------------------------------------------------
extern "C" void kernel_launch(void* const* d_in, const int* in_sizes, int n_in,
                              void* d_out, int out_size) {
    const float* x     = (const float*)d_in[0];
    const float* gamma = (const float*)d_in[1];
    const float* wq    = (const float*)d_in[2];
    const float* wk    = (const float*)d_in[3];
    const float* wv    = (const float*)d_in[4];
    const float* wo    = (const float*)d_in[5];
    const float* bo    = (const float*)d_in[6];
    const float* wdw   = (const float*)d_in[7];
    const float* bdw   = (const float*)d_in[8];
    const float* wproj = (const float*)d_in[9];
    const float* cw0   = (const float*)d_in[10];
    const float* cb0   = (const float*)d_in[11];
    const float* cw1   = (const float*)d_in[12];
    const float* cb1   = (const float*)d_in[13];
    const float* cw2   = (const float*)d_in[14];
    const float* cb2   = (const float*)d_in[15];
    float* out = (float*)d_out;

    k_qproj<<<dim3(18, 8), 128>>>(x, wq);
    k_offsets<<<dim3(8, 12), 384>>>(x, wdw, bdw, wproj, wk, wv);
    k_attn<<<dim3(8, 144), 128>>>(cw0, cb0, cw1, cb1, cw2, cb2);
    k_outproj<<<dim3(288, 2), 256>>>(x, wo, bo, gamma, out, out_size);
}

// round 16
// speedup vs baseline: 1.1958x; 1.1958x over previous
#include <cuda_runtime.h>
#include <math.h>
#include <stdint.h>

// Problem dims
#define BB 2
#define CC 128
#define HH 48
#define WW 48
#define GG 4
#define DHD 32
#define NPIX 2304   // 48*48
#define HD 12
#define JD 144      // 12*12
#define BG 8        // B*G
#define TI 32       // query tile per attention block
#define BSTR 145    // padded bias row stride
#define H1PAD 36    // h1 tile row stride (uint32): conflict-free frag loads

// Scratch (allocation-free: __device__ globals)
__device__ float g_q[BG * DHD * NPIX];   // q per (bg, d, i)
__device__ float g_vn0[BG * JD];
__device__ float g_vn1[BG * JD];
__device__ float g_k[BG * JD * DHD];     // (bg, j, d)
__device__ float g_v[BG * JD * DHD];
__device__ float g_o[BB * CC * NPIX];    // attention head outputs

__device__ __forceinline__ uint32_t f2tf32(float x) {
    uint32_t u;
    asm("cvt.rna.tf32.f32 %0, %1;" : "=r"(u) : "f"(x));
    return u;
}

// ---------------------------------------------------------------------------
// K1: grouped 1x1 conv -> q.  grid (18, 8), block 128.
// ---------------------------------------------------------------------------
__global__ void __launch_bounds__(128)
k_qproj(const float* __restrict__ x, const float* __restrict__ wq) {
    int bg = blockIdx.y;
    int g  = bg & 3;
    int b  = bg >> 2;
    int i  = blockIdx.x * 128 + threadIdx.x;

    __shared__ __align__(16) float wqs[32 * 32];
    for (int t = threadIdx.x; t < 1024; t += 128) wqs[t] = wq[g * 1024 + t];
    __syncthreads();
    if (i >= NPIX) return;

    float acc[32];
#pragma unroll
    for (int o = 0; o < 32; o++) acc[o] = 0.f;

    const float* xp = x + (size_t)(b * CC + g * 32) * NPIX + i;
#pragma unroll 4
    for (int c = 0; c < 32; c++) {
        float xv = xp[c * NPIX];
#pragma unroll
        for (int o = 0; o < 32; o++) acc[o] = fmaf(xv, wqs[o * 32 + c], acc[o]);
    }
#pragma unroll
    for (int o = 0; o < 32; o++) g_q[(bg * 32 + o) * NPIX + i] = acc[o];
}

// ---------------------------------------------------------------------------
// K2: offsets + bilinear + k/v proj.  grid (8, 12), block 384.
// ---------------------------------------------------------------------------
__global__ void __launch_bounds__(384)
k_offsets(const float* __restrict__ x,
          const float* __restrict__ wdw, const float* __restrict__ bdw,
          const float* __restrict__ wproj,
          const float* __restrict__ wk, const float* __restrict__ wv) {
    int bg = blockIdx.x;
    int g  = bg & 3;
    int b  = bg >> 2;
    int oy = blockIdx.y;
    int t  = threadIdx.x;
    int ox = t >> 5;
    int c  = t & 31;
    int j  = oy * HD + ox;

    __shared__ float wks[32 * 33], wvs[32 * 33];
    __shared__ float kvs[12][33];

    for (int idx = t; idx < 1024; idx += 384) {
        int o = idx >> 5, cc = idx & 31;
        wks[o * 33 + cc] = wk[g * 1024 + idx];
        wvs[o * 33 + cc] = wv[g * 1024 + idx];
    }

    float s = 0.f;
    const float* qc = g_q + (size_t)(bg * 32 + c) * NPIX;
    const float* wc = wdw + c * 36;
#pragma unroll
    for (int ky = 0; ky < 6; ky++) {
        int iy = oy * 4 - 1 + ky;
        if (iy < 0 || iy >= HH) continue;
#pragma unroll
        for (int kx = 0; kx < 6; kx++) {
            int ix = ox * 4 - 1 + kx;
            if (ix < 0 || ix >= WW) continue;
            s = fmaf(qc[iy * WW + ix], wc[ky * 6 + kx], s);
        }
    }
    float tt = s + bdw[c];
    float ge = 0.5f * tt * (1.f + erff(tt * 0.70710678118654752f));
    float p0 = ge * wproj[c];
    float p1 = ge * wproj[32 + c];
#pragma unroll
    for (int off = 16; off > 0; off >>= 1) {
        p0 += __shfl_xor_sync(0xffffffffu, p0, off);
        p1 += __shfl_xor_sync(0xffffffffu, p1, off);
    }

    float px = 0.f, py = 0.f;
    if (c == 0) {
        float o0 = tanhf(p0) * 4.f;
        float o1 = tanhf(p1) * 4.f;
        float vn0 = 2.f * ((float)ox + o0) / 11.f - 1.f;
        float vn1 = 2.f * ((float)oy + o1) / 11.f - 1.f;
        g_vn0[bg * JD + j] = vn0;
        g_vn1[bg * JD + j] = vn1;
        px = ((vn0 + 1.f) * (float)WW - 1.f) * 0.5f;
        py = ((vn1 + 1.f) * (float)HH - 1.f) * 0.5f;
    }
    px = __shfl_sync(0xffffffffu, px, 0);
    py = __shfl_sync(0xffffffffu, py, 0);

    float x0 = floorf(px), y0 = floorf(py);
    float wx1 = px - x0, wy1 = py - y0;
    int ix0 = (int)x0, iy0 = (int)y0;
    float w00 = (1.f - wx1) * (1.f - wy1);
    float w10 = wx1 * (1.f - wy1);
    float w01 = (1.f - wx1) * wy1;
    float w11 = wx1 * wy1;
    bool vx0 = (ix0 >= 0) && (ix0 <= WW - 1);
    bool vx1 = (ix0 + 1 >= 0) && (ix0 + 1 <= WW - 1);
    bool vy0 = (iy0 >= 0) && (iy0 <= HH - 1);
    bool vy1 = (iy0 + 1 >= 0) && (iy0 + 1 <= HH - 1);
    int cx0 = min(max(ix0, 0), WW - 1), cx1 = min(max(ix0 + 1, 0), WW - 1);
    int cy0 = min(max(iy0, 0), HH - 1), cy1 = min(max(iy0 + 1, 0), HH - 1);

    const float* xc = x + (size_t)(b * CC + g * 32 + c) * NPIX;
    float a = 0.f;
    if (vx0 && vy0) a = fmaf(xc[cy0 * WW + cx0], w00, a);
    if (vx1 && vy0) a = fmaf(xc[cy0 * WW + cx1], w10, a);
    if (vx0 && vy1) a = fmaf(xc[cy1 * WW + cx0], w01, a);
    if (vx1 && vy1) a = fmaf(xc[cy1 * WW + cx1], w11, a);
    kvs[ox][c] = a;
    __syncthreads();

    int o = c;
    float ak = 0.f, av = 0.f;
#pragma unroll 8
    for (int cc = 0; cc < 32; cc++) {
        float kvv = kvs[ox][cc];
        ak = fmaf(kvv, wks[o * 33 + cc], ak);
        av = fmaf(kvv, wvs[o * 33 + cc], av);
    }
    g_k[(size_t)(bg * JD + j) * 32 + o] = ak;
    g_v[(size_t)(bg * JD + j) * 32 + o] = av;
}

// ---------------------------------------------------------------------------
// K3: fused attention, two phases.  grid (8, 72), block 128.  (R7 config)
//   Phase A layer-1: tf32 mma.sync.m16n8k8; h1 raw fp32 bits (HW truncation).
// ---------------------------------------------------------------------------
__global__ void __launch_bounds__(128)
k_attn(const float* __restrict__ cw0, const float* __restrict__ cb0,
       const float* __restrict__ cw1, const float* __restrict__ cb1,
       const float* __restrict__ cw2, const float* __restrict__ cb2) {
    int bg = blockIdx.x;
    int ib = blockIdx.y * TI;
    int t  = threadIdx.x;
    int wp   = t >> 5;
    int lane = t & 31;

    __shared__ __align__(16) float bias_s[TI * BSTR];
    __shared__ __align__(16) uint32_t h1s[4][32 * H1PAD];  // per-warp h1 tile (fp32 bits)
    __shared__ __align__(16) uint2 w1f[4][4][32];          // B fragments [ktile][ntile][lane]
    __shared__ float vn0s[JD], vn1s[JD];
    __shared__ float w0s[64], b0s[32], b1s[32], w2s[32];

    for (int idx = t; idx < JD; idx += 128) {
        vn0s[idx] = g_vn0[bg * JD + idx];
        vn1s[idx] = g_vn1[bg * JD + idx];
    }
    if (t < 64) w0s[t] = cw0[t];
    if (t < 32) { b0s[t] = cb0[t]; b1s[t] = cb1[t]; w2s[t] = cw2[t]; }
    for (int idx = t; idx < 512; idx += 128) {
        int kt = idx >> 7;
        int nt = (idx >> 5) & 3;
        int ln = idx & 31;
        int k  = kt * 8 + (ln & 3);
        int n  = nt * 8 + (ln >> 2);
        uint2 bfr;
        bfr.x = f2tf32(cw1[k * 32 + n]);         // b0: (k, n)
        bfr.y = f2tf32(cw1[(k + 4) * 32 + n]);   // b1: (k+4, n)
        w1f[kt][nt][ln] = bfr;
    }
    __syncthreads();

    float b2v = __ldg(cb2);

    // Per-lane epilogue constants: this lane's 8 output channels (2 per ntile).
    float b1v[8], w2v[8];
#pragma unroll
    for (int nt = 0; nt < 4; nt++) {
        int c = nt * 8 + 2 * (lane & 3);
        b1v[2 * nt]     = b1s[c];
        b1v[2 * nt + 1] = b1s[c + 1];
        w2v[2 * nt]     = w2s[c];
        w2v[2 * nt + 1] = w2s[c + 1];
    }

    uint32_t* hw = &h1s[wp][0];
    int r0 = lane >> 2;
    int c0 = lane & 3;

    // -------- Phase A: 36 passes, 32 evals per warp per pass --------
#pragma unroll 1
    for (int pass = 0; pass < 36; pass++) {
        int pbase = pass * 128 + wp * 32;
        int p  = pbase + lane;
        int il = p / JD;
        int j  = p - il * JD;
        int i  = ib + il;
        int ixq = i % WW;
        int iyq = i / WW;
        float qn0 = fmaf((float)ixq, 2.f / 47.f, -1.f);
        float qn1 = fmaf((float)iyq, 2.f / 47.f, -1.f);
        float dx = qn0 - vn0s[j];
        float dy = qn1 - vn1s[j];
        float fx = copysignf(log1pf(fabsf(dx)), dx);
        float fy = copysignf(log1pf(fabsf(dy)), dy);

        // layer 0: 2 -> 32, relu; store straight to tile (raw fp32 bits)
        uint4* dst = (uint4*)&hw[lane * H1PAD];
#pragma unroll
        for (int q = 0; q < 8; q++) {
            int c = q * 4;
            uint4 v;
            v.x = __float_as_uint(fmaxf(fmaf(fy, w0s[32 + c],     fmaf(fx, w0s[c],     b0s[c])),     0.f));
            v.y = __float_as_uint(fmaxf(fmaf(fy, w0s[32 + c + 1], fmaf(fx, w0s[c + 1], b0s[c + 1])), 0.f));
            v.z = __float_as_uint(fmaxf(fmaf(fy, w0s[32 + c + 2], fmaf(fx, w0s[c + 2], b0s[c + 2])), 0.f));
            v.w = __float_as_uint(fmaxf(fmaf(fy, w0s[32 + c + 3], fmaf(fx, w0s[c + 3], b0s[c + 3])), 0.f));
            dst[q] = v;
        }
        __syncwarp();

        // 32x32x32 GEMM: h2 = h1 @ W1
        float acc[2][4][4];
#pragma unroll
        for (int m = 0; m < 2; m++)
#pragma unroll
            for (int n = 0; n < 4; n++)
#pragma unroll
                for (int e = 0; e < 4; e++) acc[m][n][e] = 0.f;

#pragma unroll
        for (int kt = 0; kt < 4; kt++) {
            uint32_t a[2][4];
#pragma unroll
            for (int m = 0; m < 2; m++) {
                int rb = m * 16 + r0;
                int cb = kt * 8 + c0;
                a[m][0] = hw[rb * H1PAD + cb];
                a[m][1] = hw[(rb + 8) * H1PAD + cb];
                a[m][2] = hw[rb * H1PAD + cb + 4];
                a[m][3] = hw[(rb + 8) * H1PAD + cb + 4];
            }
#pragma unroll
            for (int nt = 0; nt < 4; nt++) {
                uint2 bfr = w1f[kt][nt][lane];
#pragma unroll
                for (int m = 0; m < 2; m++) {
                    asm volatile(
                        "mma.sync.aligned.m16n8k8.row.col.f32.tf32.tf32.f32 "
                        "{%0,%1,%2,%3}, {%4,%5,%6,%7}, {%8,%9}, {%0,%1,%2,%3};"
                        : "+f"(acc[m][nt][0]), "+f"(acc[m][nt][1]),
                          "+f"(acc[m][nt][2]), "+f"(acc[m][nt][3])
                        : "r"(a[m][0]), "r"(a[m][1]), "r"(a[m][2]), "r"(a[m][3]),
                          "r"(bfr.x), "r"(bfr.y));
                }
            }
        }
        __syncwarp();   // tile reused next pass

        // layer 2: relu(h2 + b1) . w2, reduce over the 4 lanes sharing a row.
        float ps[4];
#pragma unroll
        for (int m = 0; m < 2; m++) {
            float pa = 0.f, pb = 0.f;
#pragma unroll
            for (int nt = 0; nt < 4; nt++) {
                pa = fmaf(fmaxf(acc[m][nt][0] + b1v[2 * nt],     0.f), w2v[2 * nt],     pa);
                pa = fmaf(fmaxf(acc[m][nt][1] + b1v[2 * nt + 1], 0.f), w2v[2 * nt + 1], pa);
                pb = fmaf(fmaxf(acc[m][nt][2] + b1v[2 * nt],     0.f), w2v[2 * nt],     pb);
                pb = fmaf(fmaxf(acc[m][nt][3] + b1v[2 * nt + 1], 0.f), w2v[2 * nt + 1], pb);
            }
            ps[2 * m]     = pa;   // row m*16 + r0
            ps[2 * m + 1] = pb;   // row m*16 + r0 + 8
        }
#pragma unroll
        for (int s = 0; s < 4; s++) {
            ps[s] += __shfl_xor_sync(0xffffffffu, ps[s], 1);
            ps[s] += __shfl_xor_sync(0xffffffffu, ps[s], 2);
        }
        if ((lane & 3) == 0) {
#pragma unroll
            for (int s = 0; s < 4; s++) {
                int r  = ((s >> 1) * 16) + ((s & 1) * 8) + r0;
                int pe = pbase + r;
                int ile = pe / JD;
                int je  = pe - ile * JD;
                bias_s[ile * BSTR + je] = ps[s] + b2v;
            }
        }
    }
    __syncthreads();

    // -------- Phase B: attention --------
    int il = t >> 2;          // 0..31 query within tile
    int dq = t & 3;           // d-quarter: 8 dims
    int i  = ib + il;

    const float scale = 0.17677669529663687f;  // 32^-0.5
    float qreg[8];
#pragma unroll
    for (int d = 0; d < 8; d++)
        qreg[d] = g_q[(bg * 32 + dq * 8 + d) * NPIX + i] * scale;

    const float4* kb = (const float4*)(g_k + (size_t)bg * JD * 32);
    const float4* vb = (const float4*)(g_v + (size_t)bg * JD * 32);

    float m = -INFINITY, ssum = 0.f;
    float acc[8];
#pragma unroll
    for (int d = 0; d < 8; d++) acc[d] = 0.f;

#pragma unroll 2
    for (int j = 0; j < JD; j++) {
        float4 k0 = __ldg(&kb[j * 8 + dq * 2]);
        float4 k1 = __ldg(&kb[j * 8 + dq * 2 + 1]);
        float sim = qreg[0] * k0.x;
        sim = fmaf(qreg[1], k0.y, sim);
        sim = fmaf(qreg[2], k0.z, sim);
        sim = fmaf(qreg[3], k0.w, sim);
        sim = fmaf(qreg[4], k1.x, sim);
        sim = fmaf(qreg[5], k1.y, sim);
        sim = fmaf(qreg[6], k1.z, sim);
        sim = fmaf(qreg[7], k1.w, sim);
        sim += __shfl_xor_sync(0xffffffffu, sim, 1);
        sim += __shfl_xor_sync(0xffffffffu, sim, 2);

        float logit = sim + bias_s[il * BSTR + j];

        float nm   = fmaxf(m, logit);
        float corr = __expf(m - nm);
        float p    = __expf(logit - nm);
        ssum = fmaf(ssum, corr, p);

        float4 v0 = __ldg(&vb[j * 8 + dq * 2]);
        float4 v1 = __ldg(&vb[j * 8 + dq * 2 + 1]);
        acc[0] = fmaf(p, v0.x, acc[0] * corr);
        acc[1] = fmaf(p, v0.y, acc[1] * corr);
        acc[2] = fmaf(p, v0.z, acc[2] * corr);
        acc[3] = fmaf(p, v0.w, acc[3] * corr);
        acc[4] = fmaf(p, v1.x, acc[4] * corr);
        acc[5] = fmaf(p, v1.y, acc[5] * corr);
        acc[6] = fmaf(p, v1.z, acc[6] * corr);
        acc[7] = fmaf(p, v1.w, acc[7] * corr);
        m = nm;
    }

    float inv = 1.f / ssum;
#pragma unroll
    for (int d = 0; d < 8; d++)
        g_o[(bg * 32 + dq * 8 + d) * NPIX + i] = acc[d] * inv;
}

// ---------------------------------------------------------------------------
// K4: output 1x1 projection + residual; writes both tuple outputs.
//     grid (288, 2), block 256. Tile = 8 pixels; thread = (px, 4 out chans).
//     (R14 config: measured 17.6us)
// ---------------------------------------------------------------------------
__global__ void __launch_bounds__(256)
k_outproj(const float* __restrict__ x, const float* __restrict__ wo,
          const float* __restrict__ bo, const float* __restrict__ gamma,
          float* __restrict__ out, int out_size) {
    int b    = blockIdx.y;
    int t    = threadIdx.x;
    int px   = t & 7;
    int ochg = t >> 3;          // 0..31 -> out channels [ochg*4, ochg*4+4)
    int ibase = blockIdx.x * 8;

    __shared__ __align__(16) float os_s[8][132];   // [px][c], padded
    for (int idx = t; idx < 1024; idx += 256) {
        int c = idx >> 3, pl = idx & 7;
        os_s[pl][c] = g_o[(size_t)(b * CC + c) * NPIX + ibase + pl];
    }
    __syncthreads();

    float acc[4];
#pragma unroll
    for (int o = 0; o < 4; o++) acc[o] = bo[ochg * 4 + o];

#pragma unroll 4
    for (int c4 = 0; c4 < 32; c4++) {
        float4 os4 = *(const float4*)&os_s[px][c4 * 4];
#pragma unroll
        for (int o = 0; o < 4; o++) {
            float4 w4 = __ldg((const float4*)&wo[(ochg * 4 + o) * CC + c4 * 4]);
            acc[o] = fmaf(os4.x, w4.x, acc[o]);
            acc[o] = fmaf(os4.y, w4.y, acc[o]);
            acc[o] = fmaf(os4.z, w4.z, acc[o]);
            acc[o] = fmaf(os4.w, w4.w, acc[o]);
        }
    }

    float gm = gamma[0];
    const int n1 = BB * CC * NPIX;
    int i = ibase + px;
#pragma unroll
    for (int o = 0; o < 4; o++) {
        int ch  = ochg * 4 + o;
        int idx = (b * CC + ch) * NPIX + i;
        float att = acc[o];
        if (idx < out_size) out[idx] = fmaf(gm, att, x[idx]);
        int idx2 = n1 + idx;
        if (idx2 < out_size) out[idx2] = att;
    }
}

// ---------------------------------------------------------------------------
extern "C" void kernel_launch(void* const* d_in, const int* in_sizes, int n_in,
                              void* d_out, int out_size) {
    const float* x     = (const float*)d_in[0];
    const float* gamma = (const float*)d_in[1];
    const float* wq    = (const float*)d_in[2];
    const float* wk    = (const float*)d_in[3];
    const float* wv    = (const float*)d_in[4];
    const float* wo    = (const float*)d_in[5];
    const float* bo    = (const float*)d_in[6];
    const float* wdw   = (const float*)d_in[7];
    const float* bdw   = (const float*)d_in[8];
    const float* wproj = (const float*)d_in[9];
    const float* cw0   = (const float*)d_in[10];
    const float* cb0   = (const float*)d_in[11];
    const float* cw1   = (const float*)d_in[12];
    const float* cb1   = (const float*)d_in[13];
    const float* cw2   = (const float*)d_in[14];
    const float* cb2   = (const float*)d_in[15];
    float* out = (float*)d_out;

    k_qproj<<<dim3(18, 8), 128>>>(x, wq);
    k_offsets<<<dim3(8, 12), 384>>>(x, wdw, bdw, wproj, wk, wv);
    k_attn<<<dim3(8, 72), 128>>>(cw0, cb0, cw1, cb1, cw2, cb2);
    k_outproj<<<dim3(288, 2), 256>>>(x, wo, bo, gamma, out, out_size);
}